// round 2
// baseline (speedup 1.0000x reference)
#include <cuda_runtime.h>
#include <math.h>
#include <float.h>

#define CH   64
#define IMG_W 256
#define IMG_H 256
#define HWN  65536
#define NB   8

// ---------------- scratch (device globals: no allocation allowed) ----------
__device__ float g_r1[NB * CH * HWN];     // conv1+prelu output
__device__ float g_r [NB * CH * HWN];     // conv2 output (pre-attention "r")
__device__ float g_avg[NB * HWN];         // channel mean per pixel
__device__ float g_max[NB * HWN];         // channel max  per pixel
__device__ float g_sg [NB * HWN];         // sigmoid(spatial attention map)
__device__ float g_chansum[NB * CH];      // global channel sums (atomics)
__device__ float g_K1[NB * CH * CH];      // hyper kernel, SA half
__device__ float g_K2[NB * CH * CH];      // hyper kernel, CA half (pre-scaled by cv)

__device__ __forceinline__ int reflect(int v, int n) {
    if (v < 0) v = -v;
    if (v >= n) v = 2 * n - 2 - v;
    return v;
}

// ---------------- init ----------------
__global__ void init_kernel() {
    int i = blockIdx.x * blockDim.x + threadIdx.x;
    if (i < NB * CH) g_chansum[i] = 0.0f;
}

// ---------------- 3x3 conv, reflect pad, fused epilogues --------------------
// Tile: 16(w) x 8(h) pixels, all 64 out channels. 256 threads:
// tx = tid&15 picks pixel column, ty = tid>>4 picks 4 out channels.
template <bool IS_CONV2>
__global__ __launch_bounds__(256)
void conv3x3_kernel(const float* __restrict__ in,
                    const float* __restrict__ wgt,   // [O][I][3][3]
                    const float* __restrict__ bias,
                    const float* __restrict__ prelu_a,
                    float* __restrict__ out)
{
    __shared__ float sin_t[10][18];
    __shared__ float sw[64][9];
    __shared__ float psum[16][8][16];   // reused for sum then max reduction

    const int tid = threadIdx.x;
    const int tx  = tid & 15;
    const int ty  = tid >> 4;
    const int x0  = blockIdx.x * 16;
    const int y0  = blockIdx.y * 8;
    const int b   = blockIdx.z;
    const int ob  = ty * 4;

    float acc[8][4];
#pragma unroll
    for (int h = 0; h < 8; h++)
#pragma unroll
        for (int j = 0; j < 4; j++) acc[h][j] = 0.0f;

    for (int ci = 0; ci < CH; ci++) {
        __syncthreads();
        // stage input tile (with reflect halo)
        if (tid < 180) {
            int lx = tid % 18, ly = tid / 18;
            int gx = reflect(x0 + lx - 1, IMG_W);
            int gy = reflect(y0 + ly - 1, IMG_H);
            sin_t[ly][lx] = in[((size_t)(b * CH + ci)) * HWN + gy * IMG_W + gx];
        }
        // stage weights for this input channel: [64 out][9]
        for (int i = tid; i < 576; i += 256) {
            int o = i / 9, k = i % 9;
            sw[o][k] = wgt[o * (CH * 9) + ci * 9 + k];
        }
        __syncthreads();

        float wr[4][9];
#pragma unroll
        for (int j = 0; j < 4; j++)
#pragma unroll
            for (int k = 0; k < 9; k++) wr[j][k] = sw[ob + j][k];

#pragma unroll
        for (int h = 0; h < 8; h++) {
#pragma unroll
            for (int ky = 0; ky < 3; ky++) {
#pragma unroll
                for (int kx = 0; kx < 3; kx++) {
                    float v = sin_t[h + ky][tx + kx];
#pragma unroll
                    for (int j = 0; j < 4; j++)
                        acc[h][j] = fmaf(v, wr[j][ky * 3 + kx], acc[h][j]);
                }
            }
        }
    }

    float bv[4];
#pragma unroll
    for (int j = 0; j < 4; j++) bv[j] = bias[ob + j];

    if (!IS_CONV2) {
        float av[4];
#pragma unroll
        for (int j = 0; j < 4; j++) av[j] = prelu_a[ob + j];
#pragma unroll
        for (int h = 0; h < 8; h++) {
#pragma unroll
            for (int j = 0; j < 4; j++) {
                float v = acc[h][j] + bv[j];
                v = v > 0.0f ? v : av[j] * v;
                out[((size_t)(b * CH + ob + j)) * HWN + (y0 + h) * IMG_W + x0 + tx] = v;
            }
        }
    } else {
        float sumh[8], maxh[8];
        float csum[4] = {0.f, 0.f, 0.f, 0.f};
#pragma unroll
        for (int h = 0; h < 8; h++) {
            float s4 = 0.0f, m4 = -FLT_MAX;
#pragma unroll
            for (int j = 0; j < 4; j++) {
                float v = acc[h][j] + bv[j];
                out[((size_t)(b * CH + ob + j)) * HWN + (y0 + h) * IMG_W + x0 + tx] = v;
                s4 += v;
                m4 = fmaxf(m4, v);
                csum[j] += v;
            }
            sumh[h] = s4; maxh[h] = m4;
        }
        // per-pixel channel mean
        __syncthreads();
#pragma unroll
        for (int h = 0; h < 8; h++) psum[ty][h][tx] = sumh[h];
        __syncthreads();
        if (tid < 128) {
            int h = tid >> 4, xx = tid & 15;
            float s = 0.0f;
#pragma unroll
            for (int t = 0; t < 16; t++) s += psum[t][h][xx];
            g_avg[b * HWN + (y0 + h) * IMG_W + x0 + xx] = s * (1.0f / CH);
        }
        __syncthreads();
#pragma unroll
        for (int h = 0; h < 8; h++) psum[ty][h][tx] = maxh[h];
        __syncthreads();
        if (tid < 128) {
            int h = tid >> 4, xx = tid & 15;
            float m = -FLT_MAX;
#pragma unroll
            for (int t = 0; t < 16; t++) m = fmaxf(m, psum[t][h][xx]);
            g_max[b * HWN + (y0 + h) * IMG_W + x0 + xx] = m;
        }
        // global channel sums: shuffle-reduce over tx (lane bits 0..3)
#pragma unroll
        for (int off = 8; off > 0; off >>= 1)
#pragma unroll
            for (int j = 0; j < 4; j++)
                csum[j] += __shfl_xor_sync(0xFFFFFFFFu, csum[j], off);
        if (tx == 0) {
#pragma unroll
            for (int j = 0; j < 4; j++)
                atomicAdd(&g_chansum[b * CH + ob + j], csum[j]);
        }
    }
}

// ---------------- spatial attention conv (2ch -> 1ch, sigmoid) -------------
__global__ __launch_bounds__(256)
void sa_kernel(const float* __restrict__ sa_w, const float* __restrict__ sa_b)
{
    int p = blockIdx.x * 256 + threadIdx.x;
    int b = blockIdx.y;
    int x = p & (IMG_W - 1);
    int y = p >> 8;
    float s = sa_b[0];
#pragma unroll
    for (int ky = 0; ky < 3; ky++) {
        int gy = reflect(y + ky - 1, IMG_H);
#pragma unroll
        for (int kx = 0; kx < 3; kx++) {
            int gx = reflect(x + kx - 1, IMG_W);
            int q = b * HWN + gy * IMG_W + gx;
            s = fmaf(sa_w[ky * 3 + kx],     g_avg[q], s);
            s = fmaf(sa_w[9 + ky * 3 + kx], g_max[q], s);
        }
    }
    g_sg[b * HWN + p] = 1.0f / (1.0f + expf(-s));
}

// ---------------- per-batch small dense math (CA MLP + hyper kernel net) ---
__global__ __launch_bounds__(256)
void small_kernel(const float* __restrict__ h_in,
                  const float* __restrict__ ca_w1, const float* __restrict__ ca_b1,
                  const float* __restrict__ ca_a,
                  const float* __restrict__ ca_w2, const float* __restrict__ ca_b2,
                  const float* __restrict__ fc_w,  const float* __restrict__ fc_b,
                  const float* __restrict__ k1_w,  const float* __restrict__ k1_b,
                  const float* __restrict__ k2_w,  const float* __restrict__ k2_b,
                  const float* __restrict__ k3_w,  const float* __restrict__ k3_b)
{
    __shared__ float g[64], t1[32], cv[64], hv[16], t0[16], ta[32], tb[32];
    const int b = blockIdx.x;
    const int tid = threadIdx.x;

    if (tid < 64) g[tid] = g_chansum[b * CH + tid] * (1.0f / HWN);
    if (tid < 16) hv[tid] = h_in[b * 16 + tid];
    __syncthreads();

    if (tid < 32) {               // CA fc1 + PReLU
        float s = ca_b1[tid];
        for (int c = 0; c < 64; c++) s = fmaf(ca_w1[tid * 64 + c], g[c], s);
        t1[tid] = s > 0.0f ? s : ca_a[tid] * s;
    }
    if (tid >= 32 && tid < 48) {  // hyper fc + leaky
        int j = tid - 32;
        float s = fc_b[j];
        for (int c = 0; c < 16; c++) s = fmaf(fc_w[j * 16 + c], hv[c], s);
        t0[j] = s >= 0.0f ? s : 0.01f * s;
    }
    __syncthreads();

    if (tid < 64) {               // CA fc2 + sigmoid
        float s = ca_b2[tid];
        for (int j = 0; j < 32; j++) s = fmaf(ca_w2[tid * 32 + j], t1[j], s);
        cv[tid] = 1.0f / (1.0f + expf(-s));
    }
    if (tid >= 64 && tid < 96) {  // hyper k1 + leaky
        int j = tid - 64;
        float s = k1_b[j];
        for (int c = 0; c < 16; c++) s = fmaf(k1_w[j * 16 + c], t0[c], s);
        ta[j] = s >= 0.0f ? s : 0.01f * s;
    }
    __syncthreads();

    if (tid < 32) {               // hyper k2 + leaky
        float s = k2_b[tid];
        for (int j = 0; j < 32; j++) s = fmaf(k2_w[tid * 32 + j], ta[j], s);
        tb[tid] = s >= 0.0f ? s : 0.01f * s;
    }
    __syncthreads();

    // hyper k3: 8192 outputs -> K1 (SA half) and K2' = K2 * cv (CA half)
    for (int idx = tid; idx < 8192; idx += 256) {
        float s = k3_b[idx];
        for (int j = 0; j < 32; j++) s = fmaf(k3_w[idx * 32 + j], tb[j], s);
        int o = idx >> 7, i = idx & 127;
        if (i < 64) g_K1[(b * CH + o) * CH + i] = s;
        else        g_K2[(b * CH + o) * CH + (i - 64)] = s * cv[i - 64];
    }
}

// ---------------- final: dual 64x64 matvec per pixel + residual ------------
// y[o] = sg(p) * (K1[o,:] . r) + (K2'[o,:] . r) + hc_bias[o]; out = x + y
// Block: 128 pixels, 256 threads: og = tid>>5 picks 8 out chans, lane picks
// 4 pixels (stride-32 for coalesced stores).
__global__ __launch_bounds__(256)
void final_kernel(const float* __restrict__ hc_bias,
                  const float* __restrict__ x,
                  float* __restrict__ out)
{
    extern __shared__ float sm[];
    float* sK1 = sm;             // 4096
    float* sK2 = sm + 4096;      // 4096
    float* sr  = sm + 8192;      // 64 x 128
    float* ssg = sm + 16384;     // 128

    const int tid = threadIdx.x;
    const int b   = blockIdx.y;
    const int p0  = blockIdx.x * 128;

    for (int i = tid; i < 4096; i += 256) {
        sK1[i] = g_K1[b * 4096 + i];
        sK2[i] = g_K2[b * 4096 + i];
    }
    for (int i = tid; i < 8192; i += 256) {
        int c = i >> 7, p = i & 127;
        sr[i] = g_r[((size_t)(b * CH + c)) * HWN + p0 + p];
    }
    if (tid < 128) ssg[tid] = g_sg[b * HWN + p0 + tid];
    __syncthreads();

    const int og = tid >> 5;
    const int lane = tid & 31;

    float accA[8][4], accB[8][4];
#pragma unroll
    for (int o = 0; o < 8; o++)
#pragma unroll
        for (int j = 0; j < 4; j++) { accA[o][j] = 0.0f; accB[o][j] = 0.0f; }

#pragma unroll 4
    for (int c = 0; c < 64; c++) {
        float rv[4];
#pragma unroll
        for (int j = 0; j < 4; j++) rv[j] = sr[c * 128 + lane + 32 * j];
#pragma unroll
        for (int o = 0; o < 8; o++) {
            float wa = sK1[(og * 8 + o) * 64 + c];
            float wb = sK2[(og * 8 + o) * 64 + c];
#pragma unroll
            for (int j = 0; j < 4; j++) {
                accA[o][j] = fmaf(rv[j], wa, accA[o][j]);
                accB[o][j] = fmaf(rv[j], wb, accB[o][j]);
            }
        }
    }

#pragma unroll
    for (int o = 0; o < 8; o++) {
        int oc = og * 8 + o;
        float hb = hc_bias[oc];
#pragma unroll
        for (int j = 0; j < 4; j++) {
            int pl = lane + 32 * j;
            size_t idx = ((size_t)(b * CH + oc)) * HWN + p0 + pl;
            float y = fmaf(ssg[pl], accA[o][j], accB[o][j]) + hb;
            out[idx] = x[idx] + y;
        }
    }
}

// ---------------- launch ----------------------------------------------------
extern "C" void kernel_launch(void* const* d_in, const int* in_sizes, int n_in,
                              void* d_out, int out_size)
{
    const float* x       = (const float*)d_in[0];
    const float* h       = (const float*)d_in[1];
    const float* conv1_w = (const float*)d_in[2];
    const float* conv1_b = (const float*)d_in[3];
    const float* prelu_a = (const float*)d_in[4];
    const float* conv2_w = (const float*)d_in[5];
    const float* conv2_b = (const float*)d_in[6];
    const float* sa_w    = (const float*)d_in[7];
    const float* sa_b    = (const float*)d_in[8];
    const float* ca_w1   = (const float*)d_in[9];
    const float* ca_b1   = (const float*)d_in[10];
    const float* ca_a    = (const float*)d_in[11];
    const float* ca_w2   = (const float*)d_in[12];
    const float* ca_b2   = (const float*)d_in[13];
    const float* fc_w    = (const float*)d_in[14];
    const float* fc_b    = (const float*)d_in[15];
    const float* k1_w    = (const float*)d_in[16];
    const float* k1_b    = (const float*)d_in[17];
    const float* k2_w    = (const float*)d_in[18];
    const float* k2_b    = (const float*)d_in[19];
    const float* k3_w    = (const float*)d_in[20];
    const float* k3_b    = (const float*)d_in[21];
    const float* hc_bias = (const float*)d_in[22];
    float* out = (float*)d_out;

    float* r1 = nullptr;
    float* r  = nullptr;
    cudaGetSymbolAddress((void**)&r1, g_r1);
    cudaGetSymbolAddress((void**)&r,  g_r);

    static bool attr_set = false;
    if (!attr_set) {
        cudaFuncSetAttribute(final_kernel,
                             cudaFuncAttributeMaxDynamicSharedMemorySize,
                             (16384 + 128) * (int)sizeof(float));
        attr_set = true;
    }

    init_kernel<<<2, 256>>>();

    dim3 cgrid(IMG_W / 16, IMG_H / 8, NB);
    conv3x3_kernel<false><<<cgrid, 256>>>(x,  conv1_w, conv1_b, prelu_a, r1);
    conv3x3_kernel<true ><<<cgrid, 256>>>(r1, conv2_w, conv2_b, prelu_a, r);

    sa_kernel<<<dim3(HWN / 256, NB), 256>>>(sa_w, sa_b);

    small_kernel<<<NB, 256>>>(h, ca_w1, ca_b1, ca_a, ca_w2, ca_b2,
                              fc_w, fc_b, k1_w, k1_b, k2_w, k2_b, k3_w, k3_b);

    final_kernel<<<dim3(HWN / 128, NB), 256,
                   (16384 + 128) * sizeof(float)>>>(hc_bias, x, out);
}

// round 3
// speedup vs baseline: 2.2284x; 2.2284x over previous
#include <cuda_runtime.h>
#include <cuda_bf16.h>
#include <math.h>
#include <float.h>
#include <stdint.h>

#define CH   64
#define IMG_W 256
#define IMG_H 256
#define HWN  65536
#define NB   8

// ---------------- scratch (device globals: no allocation allowed) ----------
__device__ float g_r1[NB * CH * HWN];     // conv1+prelu output
__device__ float g_r [NB * CH * HWN];     // conv2 output (pre-attention "r")
__device__ float g_avg[NB * HWN];         // channel mean per pixel
__device__ float g_max[NB * HWN];         // channel max  per pixel
__device__ float g_sg [NB * HWN];         // sigmoid(spatial attention map)
__device__ float g_chansum[NB * CH];      // global channel sums (atomics)
__device__ float g_K1[NB * CH * CH];      // hyper kernel, SA half
__device__ float g_K2[NB * CH * CH];      // hyper kernel, CA half (pre-scaled by cv)
__device__ __nv_bfloat16 g_Wpack[2 * 9 * 2 * 64 * 64];  // prepacked conv weights hi/lo

__device__ __forceinline__ int reflect(int v, int n) {
    if (v < 0) v = -v;
    if (v >= n) v = 2 * n - 2 - v;
    return v;
}

__device__ __forceinline__ uint32_t s2u(const void* p) {
    return (uint32_t)__cvta_generic_to_shared(p);
}

__device__ __forceinline__ void ldsm_x4(uint32_t addr, uint32_t& r0, uint32_t& r1,
                                        uint32_t& r2, uint32_t& r3) {
    asm volatile("ldmatrix.sync.aligned.m8n8.x4.shared.b16 {%0,%1,%2,%3}, [%4];"
                 : "=r"(r0), "=r"(r1), "=r"(r2), "=r"(r3) : "r"(addr));
}
__device__ __forceinline__ void ldsm_x2(uint32_t addr, uint32_t& r0, uint32_t& r1) {
    asm volatile("ldmatrix.sync.aligned.m8n8.x2.shared.b16 {%0,%1}, [%2];"
                 : "=r"(r0), "=r"(r1) : "r"(addr));
}
__device__ __forceinline__ void mma16816(float* c, uint32_t a0, uint32_t a1,
                                         uint32_t a2, uint32_t a3,
                                         uint32_t b0, uint32_t b1) {
    asm volatile("mma.sync.aligned.m16n8k16.row.col.f32.bf16.bf16.f32 "
                 "{%0,%1,%2,%3}, {%4,%5,%6,%7}, {%8,%9}, {%0,%1,%2,%3};"
                 : "+f"(c[0]), "+f"(c[1]), "+f"(c[2]), "+f"(c[3])
                 : "r"(a0), "r"(a1), "r"(a2), "r"(a3), "r"(b0), "r"(b1));
}

// ---------------- init ----------------
__global__ void init_kernel() {
    int i = blockIdx.x * blockDim.x + threadIdx.x;
    if (i < NB * CH) g_chansum[i] = 0.0f;
}

// ---------------- weight prepack: fp32 OIHW -> bf16 hi/lo, [cv][tap][chunk][oc][kk]
__global__ __launch_bounds__(256)
void wpack_kernel(const float* __restrict__ w1, const float* __restrict__ w2) {
    int idx = blockIdx.x * 256 + threadIdx.x;       // < 73728
    if (idx >= 73728) return;
    int ch5 = idx & 31;
    int r   = idx >> 5;        // (((cv*9+t)*2+c2)*64 + oc)
    int oc  = r & 63;
    int r2  = r >> 6;
    int c2  = r2 & 1;
    int r3  = r2 >> 1;         // cv*9 + t
    int t   = r3 % 9;
    int cv  = r3 / 9;
    const float* w = cv ? w2 : w1;
    float v = w[oc * 576 + (c2 * 32 + ch5) * 9 + t];
    __nv_bfloat16 hi = __float2bfloat16(v);
    __nv_bfloat16 lo = __float2bfloat16(v - __bfloat162float(hi));
    __nv_bfloat16* dst = g_Wpack + (size_t)r * 64;
    dst[ch5]      = hi;
    dst[32 + ch5] = lo;
}

// ---------------- tensor-core 3x3 conv (dual-bf16, reflect pad) -------------
// CTA: 128 pixels (x-strip of one image row) x 64 out channels. 8 warps 4x2.
// K enumerated as (tap 9) x (ch chunk 2) x (3 precision sweeps) x (2 k16 steps).
#define PK 72           // slab pitch in bf16 (64 data + 8 pad -> 144B rows)
#define PW 72
#define WOFF 56320      // byte offset of W buffer in dynamic smem
#define SMEM_BYTES 65536

template <bool IS_CONV2>
__global__ __launch_bounds__(256)
void conv_mma_kernel(const float* __restrict__ in,
                     const __nv_bfloat16* __restrict__ wpack,
                     const float* __restrict__ bias,
                     const float* __restrict__ prelu_a,
                     float* __restrict__ out)
{
    extern __shared__ char smem[];
    __nv_bfloat16* slab = (__nv_bfloat16*)smem;            // 390 rows x PK
    __nv_bfloat16* wbuf = (__nv_bfloat16*)(smem + WOFF);   // 64 rows x PW
    float* st = (float*)smem;                              // epilogue transpose (reuse)
    __shared__ float sbias[64], sact[64];

    const int tid  = threadIdx.x;
    const int lane = tid & 31;
    const int wid  = tid >> 5;
    const int wm   = wid & 3;      // pixel-dim warp coord (4)
    const int wn   = wid >> 2;     // oc-dim warp coord (2)
    const int x0   = blockIdx.x * 128;
    const int y0   = blockIdx.y;
    const int b    = blockIdx.z;

    if (tid < 64) { sbias[tid] = bias[tid]; sact[tid] = IS_CONV2 ? 0.f : prelu_a[tid]; }

    float acc[2][4][4];
#pragma unroll
    for (int f = 0; f < 2; f++)
#pragma unroll
        for (int g = 0; g < 4; g++)
#pragma unroll
            for (int c = 0; c < 4; c++) acc[f][g][c] = 0.0f;

    const uint32_t slab_u = s2u(slab);
    const uint32_t wbuf_u = s2u(wbuf);

    for (int c2 = 0; c2 < 2; c2++) {
        __syncthreads();
        // stage input slab: 32 channels, 3 rows x 130 px (reflect halo), hi+lo
        for (int idx = tid; idx < 32 * 390; idx += 256) {
            int ch  = idx / 390;
            int rem = idx - ch * 390;
            int r3  = rem / 130;
            int i   = rem - r3 * 130;
            int ry  = reflect(y0 + r3 - 1, IMG_H);
            int rx  = reflect(x0 + i - 1, IMG_W);
            float v = in[((size_t)(b * CH + c2 * 32 + ch)) * HWN + ry * IMG_W + rx];
            __nv_bfloat16 hi = __float2bfloat16(v);
            __nv_bfloat16 lo = __float2bfloat16(v - __bfloat162float(hi));
            int row = r3 * 130 + i;
            slab[row * PK + ch]      = hi;
            slab[row * PK + 32 + ch] = lo;
        }
        for (int t = 0; t < 9; t++) {
            __syncthreads();
            // stage W tap tile [64 oc][64 kk] (hi 0-31, lo 32-63)
            const __nv_bfloat16* wsrc = wpack + (((size_t)t * 2 + c2) << 12);
            for (int idx = tid; idx < 4096; idx += 256)
                wbuf[(idx >> 6) * PW + (idx & 63)] = wsrc[idx];
            __syncthreads();

            const int dy = t / 3 - 1;
            const int dx = t - (t / 3) * 3 - 1;
            const int rowbase = (dy + 1) * 130 + dx + 1;
#pragma unroll
            for (int s = 0; s < 3; s++) {
                const int Aoff = (s == 1) ? 32 : 0;
                const int Woff = (s == 2) ? 32 : 0;
#pragma unroll
                for (int ks = 0; ks < 32; ks += 16) {
                    uint32_t a[2][4];
#pragma unroll
                    for (int f = 0; f < 2; f++) {
                        int row = rowbase + wm * 32 + f * 16 + (lane & 15);
                        uint32_t addr = slab_u +
                            (uint32_t)((row * PK + Aoff + ks + ((lane >> 4) << 3)) * 2);
                        ldsm_x4(addr, a[f][0], a[f][1], a[f][2], a[f][3]);
                    }
#pragma unroll
                    for (int g = 0; g < 4; g++) {
                        uint32_t b0, b1;
                        int nrow = wn * 32 + g * 8 + (lane & 7);
                        uint32_t addr = wbuf_u +
                            (uint32_t)((nrow * PW + Woff + ks + (((lane >> 3) & 1) << 3)) * 2);
                        ldsm_x2(addr, b0, b1);
                        mma16816(acc[0][g], a[0][0], a[0][1], a[0][2], a[0][3], b0, b1);
                        mma16816(acc[1][g], a[1][0], a[1][1], a[1][2], a[1][3], b0, b1);
                    }
                }
            }
        }
    }

    // ---- epilogue: transpose via smem (reusing slab region), fused stats ----
    __syncthreads();
#pragma unroll
    for (int f = 0; f < 2; f++)
#pragma unroll
        for (int g = 0; g < 4; g++)
#pragma unroll
            for (int c = 0; c < 4; c++) {
                int m = wm * 32 + f * 16 + (lane >> 2) + ((c >> 1) << 3);
                int n = wn * 32 + g * 8 + ((lane & 3) << 1) + (c & 1);
                st[n * 130 + m] = acc[f][g][c] + sbias[n];
            }
    __syncthreads();

    const size_t obase = (size_t)b * CH * HWN + (size_t)y0 * IMG_W + x0;
    if (!IS_CONV2) {
        for (int j = tid; j < 8192; j += 256) {
            int oc = j >> 7, p = j & 127;
            float v = st[oc * 130 + p];
            v = v > 0.0f ? v : sact[oc] * v;
            out[obase + (size_t)oc * HWN + p] = v;
        }
    } else {
        for (int j = tid; j < 8192; j += 256) {
            int oc = j >> 7, p = j & 127;
            out[obase + (size_t)oc * HWN + p] = st[oc * 130 + p];
        }
        if (tid < 128) {
            int p = tid;
            float s = 0.0f, mx = -FLT_MAX;
#pragma unroll 8
            for (int oc = 0; oc < 64; oc++) {
                float v = st[oc * 130 + p];
                s += v; mx = fmaxf(mx, v);
            }
            g_avg[b * HWN + y0 * IMG_W + x0 + p] = s * (1.0f / CH);
            g_max[b * HWN + y0 * IMG_W + x0 + p] = mx;
        } else if (tid < 192) {
            int oc = tid - 128;
            float s = 0.0f;
#pragma unroll 8
            for (int p = 0; p < 128; p++) s += st[oc * 130 + p];
            atomicAdd(&g_chansum[b * CH + oc], s);
        }
    }
}

// ---------------- spatial attention conv (2ch -> 1ch, sigmoid) -------------
__global__ __launch_bounds__(256)
void sa_kernel(const float* __restrict__ sa_w, const float* __restrict__ sa_b)
{
    int p = blockIdx.x * 256 + threadIdx.x;
    int b = blockIdx.y;
    int x = p & (IMG_W - 1);
    int y = p >> 8;
    float s = sa_b[0];
#pragma unroll
    for (int ky = 0; ky < 3; ky++) {
        int gy = reflect(y + ky - 1, IMG_H);
#pragma unroll
        for (int kx = 0; kx < 3; kx++) {
            int gx = reflect(x + kx - 1, IMG_W);
            int q = b * HWN + gy * IMG_W + gx;
            s = fmaf(sa_w[ky * 3 + kx],     g_avg[q], s);
            s = fmaf(sa_w[9 + ky * 3 + kx], g_max[q], s);
        }
    }
    g_sg[b * HWN + p] = 1.0f / (1.0f + expf(-s));
}

// ---------------- per-batch small dense math (CA MLP + hyper kernel net) ---
__global__ __launch_bounds__(256)
void small_kernel(const float* __restrict__ h_in,
                  const float* __restrict__ ca_w1, const float* __restrict__ ca_b1,
                  const float* __restrict__ ca_a,
                  const float* __restrict__ ca_w2, const float* __restrict__ ca_b2,
                  const float* __restrict__ fc_w,  const float* __restrict__ fc_b,
                  const float* __restrict__ k1_w,  const float* __restrict__ k1_b,
                  const float* __restrict__ k2_w,  const float* __restrict__ k2_b,
                  const float* __restrict__ k3_w,  const float* __restrict__ k3_b)
{
    __shared__ float g[64], t1[32], cv[64], hv[16], t0[16], ta[32], tb[32];
    const int b = blockIdx.x;
    const int tid = threadIdx.x;

    if (tid < 64) g[tid] = g_chansum[b * CH + tid] * (1.0f / HWN);
    if (tid < 16) hv[tid] = h_in[b * 16 + tid];
    __syncthreads();

    if (tid < 32) {               // CA fc1 + PReLU
        float s = ca_b1[tid];
        for (int c = 0; c < 64; c++) s = fmaf(ca_w1[tid * 64 + c], g[c], s);
        t1[tid] = s > 0.0f ? s : ca_a[tid] * s;
    }
    if (tid >= 32 && tid < 48) {  // hyper fc + leaky
        int j = tid - 32;
        float s = fc_b[j];
        for (int c = 0; c < 16; c++) s = fmaf(fc_w[j * 16 + c], hv[c], s);
        t0[j] = s >= 0.0f ? s : 0.01f * s;
    }
    __syncthreads();

    if (tid < 64) {               // CA fc2 + sigmoid
        float s = ca_b2[tid];
        for (int j = 0; j < 32; j++) s = fmaf(ca_w2[tid * 32 + j], t1[j], s);
        cv[tid] = 1.0f / (1.0f + expf(-s));
    }
    if (tid >= 64 && tid < 96) {  // hyper k1 + leaky
        int j = tid - 64;
        float s = k1_b[j];
        for (int c = 0; c < 16; c++) s = fmaf(k1_w[j * 16 + c], t0[c], s);
        ta[j] = s >= 0.0f ? s : 0.01f * s;
    }
    __syncthreads();

    if (tid < 32) {               // hyper k2 + leaky
        float s = k2_b[tid];
        for (int j = 0; j < 32; j++) s = fmaf(k2_w[tid * 32 + j], ta[j], s);
        tb[tid] = s >= 0.0f ? s : 0.01f * s;
    }
    __syncthreads();

    // hyper k3: 8192 outputs -> K1 (SA half) and K2' = K2 * cv (CA half)
    for (int idx = tid; idx < 8192; idx += 256) {
        float s = k3_b[idx];
        for (int j = 0; j < 32; j++) s = fmaf(k3_w[idx * 32 + j], tb[j], s);
        int o = idx >> 7, i = idx & 127;
        if (i < 64) g_K1[(b * CH + o) * CH + i] = s;
        else        g_K2[(b * CH + o) * CH + (i - 64)] = s * cv[i - 64];
    }
}

// ---------------- final: dual 64x64 matvec per pixel + residual ------------
__global__ __launch_bounds__(256)
void final_kernel(const float* __restrict__ hc_bias,
                  const float* __restrict__ x,
                  float* __restrict__ out)
{
    extern __shared__ float sm[];
    float* sK1 = sm;             // 4096
    float* sK2 = sm + 4096;      // 4096
    float* sr  = sm + 8192;      // 64 x 128
    float* ssg = sm + 16384;     // 128

    const int tid = threadIdx.x;
    const int b   = blockIdx.y;
    const int p0  = blockIdx.x * 128;

    for (int i = tid; i < 4096; i += 256) {
        sK1[i] = g_K1[b * 4096 + i];
        sK2[i] = g_K2[b * 4096 + i];
    }
    for (int i = tid; i < 8192; i += 256) {
        int c = i >> 7, p = i & 127;
        sr[i] = g_r[((size_t)(b * CH + c)) * HWN + p0 + p];
    }
    if (tid < 128) ssg[tid] = g_sg[b * HWN + p0 + tid];
    __syncthreads();

    const int og = tid >> 5;
    const int lane = tid & 31;

    float accA[8][4], accB[8][4];
#pragma unroll
    for (int o = 0; o < 8; o++)
#pragma unroll
        for (int j = 0; j < 4; j++) { accA[o][j] = 0.0f; accB[o][j] = 0.0f; }

#pragma unroll 4
    for (int c = 0; c < 64; c++) {
        float rv[4];
#pragma unroll
        for (int j = 0; j < 4; j++) rv[j] = sr[c * 128 + lane + 32 * j];
#pragma unroll
        for (int o = 0; o < 8; o++) {
            float wa = sK1[(og * 8 + o) * 64 + c];
            float wb = sK2[(og * 8 + o) * 64 + c];
#pragma unroll
            for (int j = 0; j < 4; j++) {
                accA[o][j] = fmaf(rv[j], wa, accA[o][j]);
                accB[o][j] = fmaf(rv[j], wb, accB[o][j]);
            }
        }
    }

#pragma unroll
    for (int o = 0; o < 8; o++) {
        int oc = og * 8 + o;
        float hb = hc_bias[oc];
#pragma unroll
        for (int j = 0; j < 4; j++) {
            int pl = lane + 32 * j;
            size_t idx = ((size_t)(b * CH + oc)) * HWN + p0 + pl;
            float y = fmaf(ssg[pl], accA[o][j], accB[o][j]) + hb;
            out[idx] = x[idx] + y;
        }
    }
}

// ---------------- launch ----------------------------------------------------
extern "C" void kernel_launch(void* const* d_in, const int* in_sizes, int n_in,
                              void* d_out, int out_size)
{
    const float* x       = (const float*)d_in[0];
    const float* h       = (const float*)d_in[1];
    const float* conv1_w = (const float*)d_in[2];
    const float* conv1_b = (const float*)d_in[3];
    const float* prelu_a = (const float*)d_in[4];
    const float* conv2_w = (const float*)d_in[5];
    const float* conv2_b = (const float*)d_in[6];
    const float* sa_w    = (const float*)d_in[7];
    const float* sa_b    = (const float*)d_in[8];
    const float* ca_w1   = (const float*)d_in[9];
    const float* ca_b1   = (const float*)d_in[10];
    const float* ca_a    = (const float*)d_in[11];
    const float* ca_w2   = (const float*)d_in[12];
    const float* ca_b2   = (const float*)d_in[13];
    const float* fc_w    = (const float*)d_in[14];
    const float* fc_b    = (const float*)d_in[15];
    const float* k1_w    = (const float*)d_in[16];
    const float* k1_b    = (const float*)d_in[17];
    const float* k2_w    = (const float*)d_in[18];
    const float* k2_b    = (const float*)d_in[19];
    const float* k3_w    = (const float*)d_in[20];
    const float* k3_b    = (const float*)d_in[21];
    const float* hc_bias = (const float*)d_in[22];
    float* out = (float*)d_out;

    float* r1 = nullptr;
    float* r  = nullptr;
    __nv_bfloat16* wpk = nullptr;
    cudaGetSymbolAddress((void**)&r1,  g_r1);
    cudaGetSymbolAddress((void**)&r,   g_r);
    cudaGetSymbolAddress((void**)&wpk, g_Wpack);

    static bool attr_set = false;
    if (!attr_set) {
        cudaFuncSetAttribute(conv_mma_kernel<false>,
                             cudaFuncAttributeMaxDynamicSharedMemorySize, SMEM_BYTES);
        cudaFuncSetAttribute(conv_mma_kernel<true>,
                             cudaFuncAttributeMaxDynamicSharedMemorySize, SMEM_BYTES);
        cudaFuncSetAttribute(final_kernel,
                             cudaFuncAttributeMaxDynamicSharedMemorySize,
                             (16384 + 128) * (int)sizeof(float));
        attr_set = true;
    }

    init_kernel<<<2, 256>>>();
    wpack_kernel<<<288, 256>>>(conv1_w, conv2_w);

    dim3 cgrid(IMG_W / 128, IMG_H, NB);
    conv_mma_kernel<false><<<cgrid, 256, SMEM_BYTES>>>(x,  wpk,         conv1_b, prelu_a, r1);
    conv_mma_kernel<true ><<<cgrid, 256, SMEM_BYTES>>>(r1, wpk + 73728, conv2_b, prelu_a, r);

    sa_kernel<<<dim3(HWN / 256, NB), 256>>>(sa_w, sa_b);

    small_kernel<<<NB, 256>>>(h, ca_w1, ca_b1, ca_a, ca_w2, ca_b2,
                              fc_w, fc_b, k1_w, k1_b, k2_w, k2_b, k3_w, k3_b);

    final_kernel<<<dim3(HWN / 128, NB), 256,
                   (16384 + 128) * sizeof(float)>>>(hc_bias, x, out);
}